// round 1
// baseline (speedup 1.0000x reference)
#include <cuda_runtime.h>

#define BB 2
#define NN 2048
#define MM 4096
#define DD 1024
#define HH 16
#define EE 8
#define TK 2
#define HDIM 64
#define CHUNK 512            // MM / EE
#define ATT_SCALE 0.125f     // 1/sqrt(64)

// ------------------------- scratch (device globals; no allocs) ---------------
__device__ float g_Kp[BB * MM * DD];        // projected keys
__device__ float g_Vp[BB * MM * DD];        // projected values
__device__ float g_Qp[(size_t)BB * NN * TK * DD];  // projected queries per selected pair
__device__ float g_Ao[(size_t)BB * NN * TK * DD];  // attention output per pair
__device__ float g_Go[(size_t)BB * NN * TK * DD];  // after output projection
__device__ int   g_idx[BB * NN * TK];
__device__ float g_w[BB * NN * TK];
__device__ int   g_qlist[BB * EE * NN];
__device__ int   g_slist[BB * EE * NN];
__device__ int   g_cnt[BB * EE];

// ------------------------- small kernels -------------------------------------
__global__ void zero_cnt_kernel() {
    if (threadIdx.x < BB * EE) g_cnt[threadIdx.x] = 0;
}

// one warp per query: logits = q @ Wr + br; top-2 + softmax
__global__ void router_kernel(const float* __restrict__ q,
                              const float* __restrict__ Wr,
                              const float* __restrict__ br) {
    int lane = threadIdx.x & 31;
    int qid = blockIdx.x * (blockDim.x >> 5) + (threadIdx.x >> 5);
    if (qid >= BB * NN) return;
    const float* qrow = q + (size_t)qid * DD;
    float acc[EE];
#pragma unroll
    for (int e = 0; e < EE; e++) acc[e] = 0.f;
    for (int d = lane; d < DD; d += 32) {
        float qv = qrow[d];
        const float4* w4 = reinterpret_cast<const float4*>(Wr + d * EE);
        float4 w0 = w4[0], w1 = w4[1];
        acc[0] += qv * w0.x; acc[1] += qv * w0.y;
        acc[2] += qv * w0.z; acc[3] += qv * w0.w;
        acc[4] += qv * w1.x; acc[5] += qv * w1.y;
        acc[6] += qv * w1.z; acc[7] += qv * w1.w;
    }
#pragma unroll
    for (int e = 0; e < EE; e++) {
#pragma unroll
        for (int o = 16; o > 0; o >>= 1)
            acc[e] += __shfl_xor_sync(0xffffffffu, acc[e], o);
    }
    if (lane == 0) {
        float v[EE];
#pragma unroll
        for (int e = 0; e < EE; e++) v[e] = acc[e] + br[e];
        int i0 = 0;
#pragma unroll
        for (int e = 1; e < EE; e++) if (v[e] > v[i0]) i0 = e;
        int i1 = (i0 == 0) ? 1 : 0;
#pragma unroll
        for (int e = 0; e < EE; e++) if (e != i0 && v[e] > v[i1]) i1 = e;
        float ex = __expf(v[i1] - v[i0]);
        float inv = 1.f / (1.f + ex);
        g_idx[qid * 2 + 0] = i0;
        g_idx[qid * 2 + 1] = i1;
        g_w[qid * 2 + 0] = inv;
        g_w[qid * 2 + 1] = ex * inv;
    }
}

// per-(batch,expert) compaction (atomic order is irrelevant: every row's math
// is position-independent, so results are bit-identical across runs)
__global__ void compact_kernel() {
    int t = blockIdx.x * blockDim.x + threadIdx.x;
    if (t >= BB * NN * TK) return;
    int qid = t >> 1, s = t & 1;
    int b = qid / NN, n = qid % NN;
    int e = g_idx[t];
    int pos = atomicAdd(&g_cnt[b * EE + e], 1);
    g_qlist[(b * EE + e) * NN + pos] = n;
    g_slist[(b * EE + e) * NN + pos] = s;
}

// ------------------------- 128x128x16 fp32 GEMM core -------------------------
// 256 threads, 8x8 micro-tile per thread. rowA is this thread's A-load pointer
// (already offset by its k sub-slice), nullptr => zero-fill (row out of range).
__device__ __forceinline__ void gemm_core_128(const float* rowA,
                                              const float* rowB,
                                              float (&acc)[8][8]) {
    __shared__ float As[16][128];
    __shared__ float Bs[16][128];
    int tid = threadIdx.x;
    int tx = tid & 15, ty = tid >> 4;
    int mA = tid >> 1;
    int kA = (tid & 1) * 8;
    int kB = tid >> 4;
    int nB = (tid & 15) * 8;

    for (int kt = 0; kt < DD; kt += 16) {
        float4 a0 = make_float4(0.f, 0.f, 0.f, 0.f), a1 = a0;
        if (rowA) {
            a0 = *reinterpret_cast<const float4*>(rowA + kt);
            a1 = *reinterpret_cast<const float4*>(rowA + kt + 4);
        }
        float4 b0 = *reinterpret_cast<const float4*>(rowB + (size_t)kt * DD);
        float4 b1 = *reinterpret_cast<const float4*>(rowB + (size_t)kt * DD + 4);
        __syncthreads();  // previous compute done before overwriting smem
        As[kA + 0][mA] = a0.x; As[kA + 1][mA] = a0.y;
        As[kA + 2][mA] = a0.z; As[kA + 3][mA] = a0.w;
        As[kA + 4][mA] = a1.x; As[kA + 5][mA] = a1.y;
        As[kA + 6][mA] = a1.z; As[kA + 7][mA] = a1.w;
        *reinterpret_cast<float4*>(&Bs[kB][nB])     = b0;
        *reinterpret_cast<float4*>(&Bs[kB][nB + 4]) = b1;
        __syncthreads();
#pragma unroll
        for (int k = 0; k < 16; k++) {
            float av[8], bv[8];
            *reinterpret_cast<float4*>(av)     = *reinterpret_cast<const float4*>(&As[k][ty * 8]);
            *reinterpret_cast<float4*>(av + 4) = *reinterpret_cast<const float4*>(&As[k][ty * 8 + 4]);
            *reinterpret_cast<float4*>(bv)     = *reinterpret_cast<const float4*>(&Bs[k][tx * 8]);
            *reinterpret_cast<float4*>(bv + 4) = *reinterpret_cast<const float4*>(&Bs[k][tx * 8 + 4]);
#pragma unroll
            for (int i = 0; i < 8; i++)
#pragma unroll
                for (int j = 0; j < 8; j++)
                    acc[i][j] += av[i] * bv[j];
        }
    }
}

// K/V projection: dense per (b,e) chunk. z encodes (be, K-or-V).
__global__ __launch_bounds__(256) void kvproj_kernel(
    const float* __restrict__ keys, const float* __restrict__ values,
    const float* __restrict__ Wk, const float* __restrict__ Wv,
    const float* __restrict__ bk, const float* __restrict__ bv) {
    int z = blockIdx.z;
    int which = z & 1, be = z >> 1;
    int b = be / EE, e = be % EE;
    const float* A    = (which ? values : keys) + ((size_t)b * MM + e * CHUNK) * DD;
    const float* W    = (which ? Wv : Wk) + (size_t)e * DD * DD;
    const float* bias = (which ? bv : bk) + e * DD;
    float* C          = (which ? g_Vp : g_Kp) + ((size_t)b * MM + e * CHUNK) * DD;

    int m0 = blockIdx.y * 128, n0 = blockIdx.x * 128;
    int tid = threadIdx.x, tx = tid & 15, ty = tid >> 4;
    const float* rowA = A + (size_t)(m0 + (tid >> 1)) * DD + (tid & 1) * 8;
    const float* rowB = W + (size_t)(tid >> 4) * DD + n0 + (tid & 15) * 8;

    float acc[8][8];
#pragma unroll
    for (int i = 0; i < 8; i++)
#pragma unroll
        for (int j = 0; j < 8; j++) acc[i][j] = 0.f;

    gemm_core_128(rowA, rowB, acc);

    float bvals[8];
#pragma unroll
    for (int j = 0; j < 8; j++) bvals[j] = bias[n0 + tx * 8 + j];
#pragma unroll
    for (int i = 0; i < 8; i++) {
        float* crow = C + (size_t)(m0 + ty * 8 + i) * DD + n0 + tx * 8;
        float4 o0 = make_float4(acc[i][0] + bvals[0], acc[i][1] + bvals[1],
                                acc[i][2] + bvals[2], acc[i][3] + bvals[3]);
        float4 o1 = make_float4(acc[i][4] + bvals[4], acc[i][5] + bvals[5],
                                acc[i][6] + bvals[6], acc[i][7] + bvals[7]);
        *reinterpret_cast<float4*>(crow)     = o0;
        *reinterpret_cast<float4*>(crow + 4) = o1;
    }
}

// Grouped (gathered) GEMM over per-(b,e) query lists.
// PHASE 0: A = queries[n]       -> C = g_Qp[(b,n,s)]
// PHASE 1: A = g_Ao[(b,n,s)]    -> C = g_Go[(b,n,s)]
template <int PHASE>
__global__ __launch_bounds__(256) void grouped_gemm_kernel(
    const float* __restrict__ Aglobal,
    const float* __restrict__ Wall,
    const float* __restrict__ ball) {
    int be = blockIdx.z;
    int cnt = g_cnt[be];
    int m0 = blockIdx.y * 128;
    if (m0 >= cnt) return;
    int b = be / EE, e = be % EE;
    int n0 = blockIdx.x * 128;
    int tid = threadIdx.x, tx = tid & 15, ty = tid >> 4;

    const float* W = Wall + (size_t)e * DD * DD;
    const float* bias = ball + e * DD;

    const float* rowA = nullptr;
    {
        int mg = m0 + (tid >> 1);
        if (mg < cnt) {
            int n = g_qlist[be * NN + mg];
            int s = g_slist[be * NN + mg];
            if (PHASE == 0) {
                rowA = Aglobal + ((size_t)b * NN + n) * DD + (tid & 1) * 8;
                (void)s;
            } else {
                rowA = g_Ao + (((size_t)b * NN + n) * TK + s) * DD + (tid & 1) * 8;
            }
        }
    }
    const float* rowB = W + (size_t)(tid >> 4) * DD + n0 + (tid & 15) * 8;

    float acc[8][8];
#pragma unroll
    for (int i = 0; i < 8; i++)
#pragma unroll
        for (int j = 0; j < 8; j++) acc[i][j] = 0.f;

    gemm_core_128(rowA, rowB, acc);

    float* Cdst = (PHASE == 0) ? g_Qp : g_Go;
    float bvals[8];
#pragma unroll
    for (int j = 0; j < 8; j++) bvals[j] = bias[n0 + tx * 8 + j];
#pragma unroll
    for (int i = 0; i < 8; i++) {
        int mg = m0 + ty * 8 + i;
        if (mg < cnt) {
            int n = g_qlist[be * NN + mg];
            int s = g_slist[be * NN + mg];
            float* crow = Cdst + (((size_t)b * NN + n) * TK + s) * DD + n0 + tx * 8;
            float4 o0 = make_float4(acc[i][0] + bvals[0], acc[i][1] + bvals[1],
                                    acc[i][2] + bvals[2], acc[i][3] + bvals[3]);
            float4 o1 = make_float4(acc[i][4] + bvals[4], acc[i][5] + bvals[5],
                                    acc[i][6] + bvals[6], acc[i][7] + bvals[7]);
            *reinterpret_cast<float4*>(crow)     = o0;
            *reinterpret_cast<float4*>(crow + 4) = o1;
        }
    }
}

// ------------------------- fused attention -----------------------------------
// block = (head, 16-query tile from (b,e) list, be). Full 512-key scores in smem.
#define SM_QT   (64 * 16)
#define SM_KV   (64 * 68)
#define SM_ST   (512 * 16)
#define SM_RED  256
#define ATTN_SMEM_FLOATS (SM_QT + SM_KV + SM_ST + SM_RED + 16 + 16)
#define ATTN_SMEM_BYTES  (ATTN_SMEM_FLOATS * 4)

__global__ __launch_bounds__(256) void attn_kernel() {
    extern __shared__ float sm[];
    float* qT  = sm;                 // [64 d][16 q], pre-scaled
    float* kvS = sm + SM_QT;         // K as [64 d][68 pad] / V as [64 m][68 pad]
    float* sT  = kvS + SM_KV;        // scores [512 m][16 q]
    float* red = sT + SM_ST;         // [16 seg][16 q]
    float* gmx = red + SM_RED;       // [16 q]
    float* rsm = gmx + 16;           // [16 q]

    int h = blockIdx.x, qt = blockIdx.y, be = blockIdx.z;
    int cnt = g_cnt[be];
    int q0 = qt * 16;
    if (q0 >= cnt) return;
    int nq = min(16, cnt - q0);
    int b = be / EE, e = be % EE;
    int tid = threadIdx.x;

    // load + scale Q tile (transposed)
    {
        int qi = tid & 15;
        int d0 = (tid >> 4) * 4;
        float4 v = make_float4(0.f, 0.f, 0.f, 0.f);
        if (qi < nq) {
            int n = g_qlist[be * NN + q0 + qi];
            int s = g_slist[be * NN + q0 + qi];
            v = *reinterpret_cast<const float4*>(
                g_Qp + (((size_t)b * NN + n) * TK + s) * DD + h * HDIM + d0);
        }
        qT[(d0 + 0) * 16 + qi] = v.x * ATT_SCALE;
        qT[(d0 + 1) * 16 + qi] = v.y * ATT_SCALE;
        qT[(d0 + 2) * 16 + qi] = v.z * ATT_SCALE;
        qT[(d0 + 3) * 16 + qi] = v.w * ATT_SCALE;
    }

    const float* Kb = g_Kp + ((size_t)b * MM + e * CHUNK) * DD + h * HDIM;
    const float* Vb = g_Vp + ((size_t)b * MM + e * CHUNK) * DD + h * HDIM;
    int qg  = (tid >> 5) * 2;       // query pair
    int kg  = (tid & 31) * 2;       // key pair
    int mmL = tid >> 2;             // load row
    int d0L = (tid & 3) * 16;       // load col base

    // ---- QK: 8 key tiles of 64 ----
    for (int kt = 0; kt < 8; kt++) {
        if (kt) __syncthreads();
        const float* krow = Kb + (size_t)(kt * 64 + mmL) * DD + d0L;
#pragma unroll
        for (int u = 0; u < 4; u++) {
            float4 kvv = *reinterpret_cast<const float4*>(krow + u * 4);
            kvS[(d0L + u * 4 + 0) * 68 + mmL] = kvv.x;
            kvS[(d0L + u * 4 + 1) * 68 + mmL] = kvv.y;
            kvS[(d0L + u * 4 + 2) * 68 + mmL] = kvv.z;
            kvS[(d0L + u * 4 + 3) * 68 + mmL] = kvv.w;
        }
        __syncthreads();
        float a00 = 0.f, a01 = 0.f, a10 = 0.f, a11 = 0.f;
#pragma unroll 8
        for (int d = 0; d < 64; d++) {
            float2 qv = *reinterpret_cast<const float2*>(&qT[d * 16 + qg]);
            float2 kv = *reinterpret_cast<const float2*>(&kvS[d * 68 + kg]);
            a00 += qv.x * kv.x; a01 += qv.x * kv.y;
            a10 += qv.y * kv.x; a11 += qv.y * kv.y;
        }
        int mbase = kt * 64 + kg;
        sT[(mbase + 0) * 16 + qg + 0] = a00;
        sT[(mbase + 1) * 16 + qg + 0] = a01;
        sT[(mbase + 0) * 16 + qg + 1] = a10;
        sT[(mbase + 1) * 16 + qg + 1] = a11;
    }
    __syncthreads();

    // ---- softmax per query column ----
    {
        int q = tid & 15, seg = tid >> 4;
        float mx = -1e30f;
#pragma unroll 8
        for (int i = 0; i < 32; i++) mx = fmaxf(mx, sT[(seg * 32 + i) * 16 + q]);
        red[seg * 16 + q] = mx;
        __syncthreads();
        if (tid < 16) {
            float m2 = red[tid];
            for (int s2 = 1; s2 < 16; s2++) m2 = fmaxf(m2, red[s2 * 16 + tid]);
            gmx[tid] = m2;
        }
        __syncthreads();
        float gm = gmx[q];
        float sum = 0.f;
#pragma unroll 8
        for (int i = 0; i < 32; i++) {
            float v = __expf(sT[(seg * 32 + i) * 16 + q] - gm);
            sT[(seg * 32 + i) * 16 + q] = v;
            sum += v;
        }
        red[seg * 16 + q] = sum;
        __syncthreads();
        if (tid < 16) {
            float t = 0.f;
            for (int s2 = 0; s2 < 16; s2++) t += red[s2 * 16 + tid];
            rsm[tid] = 1.f / t;
        }
        __syncthreads();
        float r = rsm[q];
#pragma unroll 8
        for (int i = 0; i < 32; i++) sT[(seg * 32 + i) * 16 + q] *= r;
    }

    // ---- AV: 8 value tiles of 64 ----
    int dg = (tid & 31) * 2;
    float o00 = 0.f, o01 = 0.f, o10 = 0.f, o11 = 0.f;
    for (int vt = 0; vt < 8; vt++) {
        __syncthreads();
        const float* vrow = Vb + (size_t)(vt * 64 + mmL) * DD + d0L;
#pragma unroll
        for (int u = 0; u < 4; u++) {
            *reinterpret_cast<float4*>(&kvS[mmL * 68 + d0L + u * 4]) =
                *reinterpret_cast<const float4*>(vrow + u * 4);
        }
        __syncthreads();
#pragma unroll 8
        for (int mm = 0; mm < 64; mm++) {
            float2 p = *reinterpret_cast<const float2*>(&sT[(vt * 64 + mm) * 16 + qg]);
            float2 v = *reinterpret_cast<const float2*>(&kvS[mm * 68 + dg]);
            o00 += p.x * v.x; o01 += p.x * v.y;
            o10 += p.y * v.x; o11 += p.y * v.y;
        }
    }

#pragma unroll
    for (int i = 0; i < 2; i++) {
        int qi = qg + i;
        if (qi < nq) {
            int n = g_qlist[be * NN + q0 + qi];
            int s = g_slist[be * NN + q0 + qi];
            float* orow = g_Ao + (((size_t)b * NN + n) * TK + s) * DD + h * HDIM + dg;
            orow[0] = i ? o10 : o00;
            orow[1] = i ? o11 : o01;
        }
    }
}

// ------------------------- final combine -------------------------------------
__global__ void combine_kernel(float* __restrict__ out) {
    int t = blockIdx.x * blockDim.x + threadIdx.x;   // BB*NN*DD/4 threads
    int qid = t >> 8;            // DD/4 = 256 float4 per row
    int d4 = (t & 255) * 4;
    float w0 = g_w[qid * 2 + 0];
    float w1 = g_w[qid * 2 + 1];
    float4 a = *reinterpret_cast<const float4*>(g_Go + ((size_t)qid * TK + 0) * DD + d4);
    float4 c = *reinterpret_cast<const float4*>(g_Go + ((size_t)qid * TK + 1) * DD + d4);
    float4 o;
    o.x = w0 * a.x + w1 * c.x;
    o.y = w0 * a.y + w1 * c.y;
    o.z = w0 * a.z + w1 * c.z;
    o.w = w0 * a.w + w1 * c.w;
    *reinterpret_cast<float4*>(out + (size_t)qid * DD + d4) = o;
}

// ------------------------- launch --------------------------------------------
extern "C" void kernel_launch(void* const* d_in, const int* in_sizes, int n_in,
                              void* d_out, int out_size) {
    const float* queries = (const float*)d_in[0];
    const float* keys    = (const float*)d_in[1];
    const float* values  = (const float*)d_in[2];
    const float* Wq = (const float*)d_in[3];
    const float* bq = (const float*)d_in[4];
    const float* Wk = (const float*)d_in[5];
    const float* bk = (const float*)d_in[6];
    const float* Wv = (const float*)d_in[7];
    const float* bv = (const float*)d_in[8];
    const float* Wo = (const float*)d_in[9];
    const float* bo = (const float*)d_in[10];
    const float* Wr = (const float*)d_in[11];
    const float* br = (const float*)d_in[12];
    float* out = (float*)d_out;
    (void)in_sizes; (void)n_in; (void)out_size;

    cudaFuncSetAttribute(attn_kernel,
                         cudaFuncAttributeMaxDynamicSharedMemorySize,
                         ATTN_SMEM_BYTES);

    zero_cnt_kernel<<<1, 32>>>();
    router_kernel<<<(BB * NN) / 8, 256>>>(queries, Wr, br);
    compact_kernel<<<(BB * NN * TK) / 256, 256>>>();
    kvproj_kernel<<<dim3(8, 4, BB * EE * 2), 256>>>(keys, values, Wk, Wv, bk, bv);
    grouped_gemm_kernel<0><<<dim3(8, 16, BB * EE), 256>>>(queries, Wq, bq);
    attn_kernel<<<dim3(HH, NN / 16, BB * EE), 256, ATTN_SMEM_BYTES>>>();
    grouped_gemm_kernel<1><<<dim3(8, 16, BB * EE), 256>>>(nullptr, Wo, bo);
    combine_kernel<<<(BB * NN * DD / 4) / 256, 256>>>(out);
}

// round 2
// speedup vs baseline: 1.2516x; 1.2516x over previous
#include <cuda_runtime.h>

#define BB 2
#define NN 2048
#define MM 4096
#define DD 1024
#define HH 16
#define EE 8
#define TK 2
#define HDIM 64
#define CHUNK 512            // MM / EE
#define ATT_SCALE 0.125f     // 1/sqrt(64)

// ------------------------- scratch (device globals; no allocs) ---------------
__device__ float g_Kp[BB * MM * DD];
__device__ float g_Vp[BB * MM * DD];
__device__ float g_Qp[(size_t)BB * NN * TK * DD];
__device__ float g_Ao[(size_t)BB * NN * TK * DD];
__device__ float g_Go[(size_t)BB * NN * TK * DD];
__device__ int   g_idx[BB * NN * TK];
__device__ float g_w[BB * NN * TK];
__device__ int   g_qlist[BB * EE * NN];
__device__ int   g_slist[BB * EE * NN];
__device__ int   g_cnt[BB * EE];

// ------------------------- cp.async helpers ----------------------------------
__device__ __forceinline__ unsigned smem_u32p(const void* p) {
    return (unsigned)__cvta_generic_to_shared(p);
}
__device__ __forceinline__ void cp_async16(unsigned dst, const float* src) {
    asm volatile("cp.async.cg.shared.global [%0], [%1], 16;\n" :: "r"(dst), "l"(src));
}
__device__ __forceinline__ void cp_commit() {
    asm volatile("cp.async.commit_group;\n" ::: "memory");
}
__device__ __forceinline__ void cp_wait_all() {
    asm volatile("cp.async.wait_group 0;\n" ::: "memory");
}

// ------------------------- small kernels -------------------------------------
__global__ void zero_cnt_kernel() {
    if (threadIdx.x < BB * EE) g_cnt[threadIdx.x] = 0;
}

__global__ void router_kernel(const float* __restrict__ q,
                              const float* __restrict__ Wr,
                              const float* __restrict__ br) {
    int lane = threadIdx.x & 31;
    int qid = blockIdx.x * (blockDim.x >> 5) + (threadIdx.x >> 5);
    if (qid >= BB * NN) return;
    const float* qrow = q + (size_t)qid * DD;
    float acc[EE];
#pragma unroll
    for (int e = 0; e < EE; e++) acc[e] = 0.f;
    for (int d = lane; d < DD; d += 32) {
        float qv = qrow[d];
        const float4* w4 = reinterpret_cast<const float4*>(Wr + d * EE);
        float4 w0 = w4[0], w1 = w4[1];
        acc[0] += qv * w0.x; acc[1] += qv * w0.y;
        acc[2] += qv * w0.z; acc[3] += qv * w0.w;
        acc[4] += qv * w1.x; acc[5] += qv * w1.y;
        acc[6] += qv * w1.z; acc[7] += qv * w1.w;
    }
#pragma unroll
    for (int e = 0; e < EE; e++) {
#pragma unroll
        for (int o = 16; o > 0; o >>= 1)
            acc[e] += __shfl_xor_sync(0xffffffffu, acc[e], o);
    }
    if (lane == 0) {
        float v[EE];
#pragma unroll
        for (int e = 0; e < EE; e++) v[e] = acc[e] + br[e];
        int i0 = 0;
#pragma unroll
        for (int e = 1; e < EE; e++) if (v[e] > v[i0]) i0 = e;
        int i1 = (i0 == 0) ? 1 : 0;
#pragma unroll
        for (int e = 0; e < EE; e++) if (e != i0 && v[e] > v[i1]) i1 = e;
        float ex = __expf(v[i1] - v[i0]);
        float inv = 1.f / (1.f + ex);
        g_idx[qid * 2 + 0] = i0;
        g_idx[qid * 2 + 1] = i1;
        g_w[qid * 2 + 0] = inv;
        g_w[qid * 2 + 1] = ex * inv;
    }
}

__global__ void compact_kernel() {
    int t = blockIdx.x * blockDim.x + threadIdx.x;
    if (t >= BB * NN * TK) return;
    int qid = t >> 1, s = t & 1;
    int b = qid / NN, n = qid % NN;
    int e = g_idx[t];
    int pos = atomicAdd(&g_cnt[b * EE + e], 1);
    g_qlist[(b * EE + e) * NN + pos] = n;
    g_slist[(b * EE + e) * NN + pos] = s;
}

// ------------------- pipelined 128x128x16 fp32 GEMM core ----------------------
// 256 threads, 8x8 micro-tile. Double-buffered smem; B via cp.async, A via
// register staging + transposed STS. One barrier per K-tile.
#define KT 16
#define NKT (DD / KT)

__device__ __forceinline__ void gemm_core_pipe(const float* rowA,  // null => zero rows
                                               const float* Bsrc0,
                                               const float* Bsrc1,
                                               float (&acc)[8][8]) {
    __shared__ float As[2][KT][128];
    __shared__ float Bs[2][KT][128];
    int tid = threadIdx.x;
    int tx = tid & 15, ty = tid >> 4;
    int mA = tid >> 1, kA = (tid & 1) * 8;
    unsigned b0d0 = smem_u32p(&Bs[0][(tid) >> 5][((tid) & 31) * 4]);
    unsigned b0d1 = smem_u32p(&Bs[0][(tid + 256) >> 5][((tid + 256) & 31) * 4]);
    unsigned b1d0 = smem_u32p(&Bs[1][(tid) >> 5][((tid) & 31) * 4]);
    unsigned b1d1 = smem_u32p(&Bs[1][(tid + 256) >> 5][((tid + 256) & 31) * 4]);

    float a[8];
#pragma unroll
    for (int j = 0; j < 8; j++) a[j] = 0.f;
    if (rowA) {
        float4 t0 = *reinterpret_cast<const float4*>(rowA);
        float4 t1 = *reinterpret_cast<const float4*>(rowA + 4);
        a[0] = t0.x; a[1] = t0.y; a[2] = t0.z; a[3] = t0.w;
        a[4] = t1.x; a[5] = t1.y; a[6] = t1.z; a[7] = t1.w;
    }
#pragma unroll
    for (int j = 0; j < 8; j++) As[0][kA + j][mA] = a[j];
    cp_async16(b0d0, Bsrc0);
    cp_async16(b0d1, Bsrc1);
    cp_commit();

    for (int kt = 0; kt < NKT; kt++) {
        int cur = kt & 1;
        cp_wait_all();
        __syncthreads();
        if (kt + 1 < NKT) {
            cp_async16(cur ? b0d0 : b1d0, Bsrc0 + (size_t)(kt + 1) * KT * DD);
            cp_async16(cur ? b0d1 : b1d1, Bsrc1 + (size_t)(kt + 1) * KT * DD);
            cp_commit();
            if (rowA) {
                float4 t0 = *reinterpret_cast<const float4*>(rowA + (kt + 1) * KT);
                float4 t1 = *reinterpret_cast<const float4*>(rowA + (kt + 1) * KT + 4);
                a[0] = t0.x; a[1] = t0.y; a[2] = t0.z; a[3] = t0.w;
                a[4] = t1.x; a[5] = t1.y; a[6] = t1.z; a[7] = t1.w;
            }
        }
#pragma unroll
        for (int k = 0; k < KT; k++) {
            float av[8], bv[8];
            *reinterpret_cast<float4*>(av)     = *reinterpret_cast<const float4*>(&As[cur][k][ty * 8]);
            *reinterpret_cast<float4*>(av + 4) = *reinterpret_cast<const float4*>(&As[cur][k][ty * 8 + 4]);
            *reinterpret_cast<float4*>(bv)     = *reinterpret_cast<const float4*>(&Bs[cur][k][tx * 8]);
            *reinterpret_cast<float4*>(bv + 4) = *reinterpret_cast<const float4*>(&Bs[cur][k][tx * 8 + 4]);
#pragma unroll
            for (int i = 0; i < 8; i++)
#pragma unroll
                for (int j = 0; j < 8; j++)
                    acc[i][j] += av[i] * bv[j];
        }
        if (kt + 1 < NKT) {
#pragma unroll
            for (int j = 0; j < 8; j++) As[cur ^ 1][kA + j][mA] = a[j];
        }
    }
}

// K/V projection
__global__ __launch_bounds__(256, 2) void kvproj_kernel(
    const float* __restrict__ keys, const float* __restrict__ values,
    const float* __restrict__ Wk, const float* __restrict__ Wv,
    const float* __restrict__ bk, const float* __restrict__ bv) {
    int z = blockIdx.z;
    int which = z & 1, be = z >> 1;
    int b = be / EE, e = be % EE;
    const float* A    = (which ? values : keys) + ((size_t)b * MM + e * CHUNK) * DD;
    const float* W    = (which ? Wv : Wk) + (size_t)e * DD * DD;
    const float* bias = (which ? bv : bk) + e * DD;
    float* C          = (which ? g_Vp : g_Kp) + ((size_t)b * MM + e * CHUNK) * DD;

    int m0 = blockIdx.y * 128, n0 = blockIdx.x * 128;
    int tid = threadIdx.x, tx = tid & 15, ty = tid >> 4;
    const float* rowA = A + (size_t)(m0 + (tid >> 1)) * DD + (tid & 1) * 8;
    const float* Bsrc0 = W + (size_t)(tid >> 5) * DD + n0 + (tid & 31) * 4;
    const float* Bsrc1 = W + (size_t)((tid + 256) >> 5) * DD + n0 + ((tid + 256) & 31) * 4;

    float acc[8][8];
#pragma unroll
    for (int i = 0; i < 8; i++)
#pragma unroll
        for (int j = 0; j < 8; j++) acc[i][j] = 0.f;

    gemm_core_pipe(rowA, Bsrc0, Bsrc1, acc);

    float bvals[8];
#pragma unroll
    for (int j = 0; j < 8; j++) bvals[j] = bias[n0 + tx * 8 + j];
#pragma unroll
    for (int i = 0; i < 8; i++) {
        float* crow = C + (size_t)(m0 + ty * 8 + i) * DD + n0 + tx * 8;
        float4 o0 = make_float4(acc[i][0] + bvals[0], acc[i][1] + bvals[1],
                                acc[i][2] + bvals[2], acc[i][3] + bvals[3]);
        float4 o1 = make_float4(acc[i][4] + bvals[4], acc[i][5] + bvals[5],
                                acc[i][6] + bvals[6], acc[i][7] + bvals[7]);
        *reinterpret_cast<float4*>(crow)     = o0;
        *reinterpret_cast<float4*>(crow + 4) = o1;
    }
}

// Grouped (gathered) GEMM. PHASE 0: queries -> g_Qp. PHASE 1: g_Ao -> g_Go.
template <int PHASE>
__global__ __launch_bounds__(256, 2) void grouped_gemm_kernel(
    const float* __restrict__ Aglobal,
    const float* __restrict__ Wall,
    const float* __restrict__ ball) {
    int be = blockIdx.z;
    int cnt = g_cnt[be];
    int m0 = blockIdx.y * 128;
    if (m0 >= cnt) return;
    int b = be / EE, e = be % EE;
    int n0 = blockIdx.x * 128;
    int tid = threadIdx.x, tx = tid & 15, ty = tid >> 4;

    const float* W = Wall + (size_t)e * DD * DD;
    const float* bias = ball + e * DD;

    const float* rowA = nullptr;
    {
        int mg = m0 + (tid >> 1);
        if (mg < cnt) {
            int n = g_qlist[be * NN + mg];
            int s = g_slist[be * NN + mg];
            if (PHASE == 0) {
                rowA = Aglobal + ((size_t)b * NN + n) * DD + (tid & 1) * 8;
                (void)s;
            } else {
                rowA = g_Ao + (((size_t)b * NN + n) * TK + s) * DD + (tid & 1) * 8;
            }
        }
    }
    const float* Bsrc0 = W + (size_t)(tid >> 5) * DD + n0 + (tid & 31) * 4;
    const float* Bsrc1 = W + (size_t)((tid + 256) >> 5) * DD + n0 + ((tid + 256) & 31) * 4;

    float acc[8][8];
#pragma unroll
    for (int i = 0; i < 8; i++)
#pragma unroll
        for (int j = 0; j < 8; j++) acc[i][j] = 0.f;

    gemm_core_pipe(rowA, Bsrc0, Bsrc1, acc);

    float* Cdst = (PHASE == 0) ? g_Qp : g_Go;
    float bvals[8];
#pragma unroll
    for (int j = 0; j < 8; j++) bvals[j] = bias[n0 + tx * 8 + j];
#pragma unroll
    for (int i = 0; i < 8; i++) {
        int mg = m0 + ty * 8 + i;
        if (mg < cnt) {
            int n = g_qlist[be * NN + mg];
            int s = g_slist[be * NN + mg];
            float* crow = Cdst + (((size_t)b * NN + n) * TK + s) * DD + n0 + tx * 8;
            float4 o0 = make_float4(acc[i][0] + bvals[0], acc[i][1] + bvals[1],
                                    acc[i][2] + bvals[2], acc[i][3] + bvals[3]);
            float4 o1 = make_float4(acc[i][4] + bvals[4], acc[i][5] + bvals[5],
                                    acc[i][6] + bvals[6], acc[i][7] + bvals[7]);
            *reinterpret_cast<float4*>(crow)     = o0;
            *reinterpret_cast<float4*>(crow + 4) = o1;
        }
    }
}

// ------------------------- fused attention (flash-style, online softmax) -----
// Block = (head, 32-query tile, be). 256 threads = 8 warps; warp owns 4 queries.
// 4 key-tiles of 128; QK micro 4q x 4k, AV micro 4q x 2d; probs via smem tile.
#define AQT  32
#define KTILE 128
#define P_KT 132
#define P_V  68
#define P_P  36
#define ATTN_SMEM_FLOATS (64 * AQT + 64 * P_KT + KTILE * P_V + KTILE * P_P)
#define ATTN_SMEM_BYTES  (ATTN_SMEM_FLOATS * 4)

__global__ __launch_bounds__(256, 2) void attn_kernel() {
    extern __shared__ float sm[];
    float* qT = sm;                    // [64 d][32 q], pre-scaled
    float* kT = qT + 64 * AQT;         // [64 d][128 k + pad]
    float* vS = kT + 64 * P_KT;        // [128 m][64 d + pad]
    float* pS = vS + KTILE * P_V;      // [128 m][32 q + pad]

    int h = blockIdx.x, qt = blockIdx.y, be = blockIdx.z;
    int cnt = g_cnt[be];
    int q0 = qt * AQT;
    if (q0 >= cnt) return;
    int nq = min(AQT, cnt - q0);
    int b = be / EE, e = be % EE;
    int tid = threadIdx.x;
    int lane = tid & 31, warp = tid >> 5;

    // load + scale Q tile (transposed [d][q])
    {
        int qi = tid & 31;
        int d0 = (tid >> 5) * 8;
        float4 v0 = make_float4(0.f, 0.f, 0.f, 0.f), v1 = v0;
        if (qi < nq) {
            int n = g_qlist[be * NN + q0 + qi];
            int s = g_slist[be * NN + q0 + qi];
            const float* qp = g_Qp + (((size_t)b * NN + n) * TK + s) * DD + h * HDIM + d0;
            v0 = *reinterpret_cast<const float4*>(qp);
            v1 = *reinterpret_cast<const float4*>(qp + 4);
        }
        qT[(d0 + 0) * AQT + qi] = v0.x * ATT_SCALE;
        qT[(d0 + 1) * AQT + qi] = v0.y * ATT_SCALE;
        qT[(d0 + 2) * AQT + qi] = v0.z * ATT_SCALE;
        qT[(d0 + 3) * AQT + qi] = v0.w * ATT_SCALE;
        qT[(d0 + 4) * AQT + qi] = v1.x * ATT_SCALE;
        qT[(d0 + 5) * AQT + qi] = v1.y * ATT_SCALE;
        qT[(d0 + 6) * AQT + qi] = v1.z * ATT_SCALE;
        qT[(d0 + 7) * AQT + qi] = v1.w * ATT_SCALE;
    }

    const float* Kb = g_Kp + ((size_t)b * MM + e * CHUNK) * DD + h * HDIM;
    const float* Vb = g_Vp + ((size_t)b * MM + e * CHUNK) * DD + h * HDIM;

    float run_mx[4], run_sum[4], o[4][2];
#pragma unroll
    for (int j = 0; j < 4; j++) {
        run_mx[j] = -1e30f; run_sum[j] = 0.f;
        o[j][0] = 0.f; o[j][1] = 0.f;
    }

    int rowL = tid >> 1;
    int dL = (tid & 1) * 32;

    for (int ktile = 0; ktile < CHUNK / KTILE; ktile++) {
        __syncthreads();   // prior AV reads of vS/pS done; qT ready (1st iter)
        // K tile: transpose into kT[d][m]
        const float* krow = Kb + (size_t)(ktile * KTILE + rowL) * DD + dL;
        const float* vrow = Vb + (size_t)(ktile * KTILE + rowL) * DD + dL;
#pragma unroll
        for (int u = 0; u < 8; u++) {
            float4 kv = *reinterpret_cast<const float4*>(krow + u * 4);
            kT[(dL + u * 4 + 0) * P_KT + rowL] = kv.x;
            kT[(dL + u * 4 + 1) * P_KT + rowL] = kv.y;
            kT[(dL + u * 4 + 2) * P_KT + rowL] = kv.z;
            kT[(dL + u * 4 + 3) * P_KT + rowL] = kv.w;
            *reinterpret_cast<float4*>(&vS[rowL * P_V + dL + u * 4]) =
                *reinterpret_cast<const float4*>(vrow + u * 4);
        }
        __syncthreads();

        // QK: 4 queries (warp) x 4 keys (lane)
        float s4[4][4];
#pragma unroll
        for (int j = 0; j < 4; j++)
#pragma unroll
            for (int i = 0; i < 4; i++) s4[j][i] = 0.f;
#pragma unroll 4
        for (int d = 0; d < HDIM; d++) {
            float4 qv = *reinterpret_cast<const float4*>(&qT[d * AQT + warp * 4]);
            float4 kv = *reinterpret_cast<const float4*>(&kT[d * P_KT + lane * 4]);
            s4[0][0] += qv.x * kv.x; s4[0][1] += qv.x * kv.y; s4[0][2] += qv.x * kv.z; s4[0][3] += qv.x * kv.w;
            s4[1][0] += qv.y * kv.x; s4[1][1] += qv.y * kv.y; s4[1][2] += qv.y * kv.z; s4[1][3] += qv.y * kv.w;
            s4[2][0] += qv.z * kv.x; s4[2][1] += qv.z * kv.y; s4[2][2] += qv.z * kv.z; s4[2][3] += qv.z * kv.w;
            s4[3][0] += qv.w * kv.x; s4[3][1] += qv.w * kv.y; s4[3][2] += qv.w * kv.z; s4[3][3] += qv.w * kv.w;
        }

        // online softmax (warp-local per query)
#pragma unroll
        for (int j = 0; j < 4; j++) {
            float mx = fmaxf(fmaxf(s4[j][0], s4[j][1]), fmaxf(s4[j][2], s4[j][3]));
#pragma unroll
            for (int off = 16; off > 0; off >>= 1)
                mx = fmaxf(mx, __shfl_xor_sync(0xffffffffu, mx, off));
            float nm = fmaxf(run_mx[j], mx);
            float fac = __expf(run_mx[j] - nm);
            run_mx[j] = nm;
            float p0 = __expf(s4[j][0] - nm);
            float p1 = __expf(s4[j][1] - nm);
            float p2 = __expf(s4[j][2] - nm);
            float p3 = __expf(s4[j][3] - nm);
            s4[j][0] = p0; s4[j][1] = p1; s4[j][2] = p2; s4[j][3] = p3;
            float ts = (p0 + p1) + (p2 + p3);
#pragma unroll
            for (int off = 16; off > 0; off >>= 1)
                ts += __shfl_xor_sync(0xffffffffu, ts, off);
            run_sum[j] = run_sum[j] * fac + ts;
            o[j][0] *= fac; o[j][1] *= fac;
        }

        // stage probs: pS[m][q]
#pragma unroll
        for (int i = 0; i < 4; i++) {
            float4 pv = make_float4(s4[0][i], s4[1][i], s4[2][i], s4[3][i]);
            *reinterpret_cast<float4*>(&pS[(lane * 4 + i) * P_P + warp * 4]) = pv;
        }
        __syncthreads();

        // AV: 4 queries (warp) x 2 dims (lane)
#pragma unroll 4
        for (int m = 0; m < KTILE; m++) {
            float4 p4 = *reinterpret_cast<const float4*>(&pS[m * P_P + warp * 4]);
            float2 v2 = *reinterpret_cast<const float2*>(&vS[m * P_V + lane * 2]);
            o[0][0] += p4.x * v2.x; o[0][1] += p4.x * v2.y;
            o[1][0] += p4.y * v2.x; o[1][1] += p4.y * v2.y;
            o[2][0] += p4.z * v2.x; o[2][1] += p4.z * v2.y;
            o[3][0] += p4.w * v2.x; o[3][1] += p4.w * v2.y;
        }
    }

#pragma unroll
    for (int j = 0; j < 4; j++) {
        int qi = warp * 4 + j;
        if (qi < nq) {
            float inv = 1.f / run_sum[j];
            int n = g_qlist[be * NN + q0 + qi];
            int s = g_slist[be * NN + q0 + qi];
            float2 ov = make_float2(o[j][0] * inv, o[j][1] * inv);
            *reinterpret_cast<float2*>(
                g_Ao + (((size_t)b * NN + n) * TK + s) * DD + h * HDIM + lane * 2) = ov;
        }
    }
}

// ------------------------- final combine -------------------------------------
__global__ void combine_kernel(float* __restrict__ out) {
    int t = blockIdx.x * blockDim.x + threadIdx.x;
    int qid = t >> 8;
    int d4 = (t & 255) * 4;
    float w0 = g_w[qid * 2 + 0];
    float w1 = g_w[qid * 2 + 1];
    float4 a = *reinterpret_cast<const float4*>(g_Go + ((size_t)qid * TK + 0) * DD + d4);
    float4 c = *reinterpret_cast<const float4*>(g_Go + ((size_t)qid * TK + 1) * DD + d4);
    float4 o;
    o.x = w0 * a.x + w1 * c.x;
    o.y = w0 * a.y + w1 * c.y;
    o.z = w0 * a.z + w1 * c.z;
    o.w = w0 * a.w + w1 * c.w;
    *reinterpret_cast<float4*>(out + (size_t)qid * DD + d4) = o;
}

// ------------------------- launch --------------------------------------------
extern "C" void kernel_launch(void* const* d_in, const int* in_sizes, int n_in,
                              void* d_out, int out_size) {
    const float* queries = (const float*)d_in[0];
    const float* keys    = (const float*)d_in[1];
    const float* values  = (const float*)d_in[2];
    const float* Wq = (const float*)d_in[3];
    const float* bq = (const float*)d_in[4];
    const float* Wk = (const float*)d_in[5];
    const float* bk = (const float*)d_in[6];
    const float* Wv = (const float*)d_in[7];
    const float* bv = (const float*)d_in[8];
    const float* Wo = (const float*)d_in[9];
    const float* bo = (const float*)d_in[10];
    const float* Wr = (const float*)d_in[11];
    const float* br = (const float*)d_in[12];
    float* out = (float*)d_out;
    (void)in_sizes; (void)n_in; (void)out_size;

    cudaFuncSetAttribute(attn_kernel,
                         cudaFuncAttributeMaxDynamicSharedMemorySize,
                         ATTN_SMEM_BYTES);

    zero_cnt_kernel<<<1, 32>>>();
    router_kernel<<<(BB * NN) / 8, 256>>>(queries, Wr, br);
    compact_kernel<<<(BB * NN * TK) / 256, 256>>>();
    kvproj_kernel<<<dim3(8, 4, BB * EE * 2), 256>>>(keys, values, Wk, Wv, bk, bv);
    grouped_gemm_kernel<0><<<dim3(8, 16, BB * EE), 256>>>(queries, Wq, bq);
    attn_kernel<<<dim3(HH, NN / AQT, BB * EE), 256, ATTN_SMEM_BYTES>>>();
    grouped_gemm_kernel<1><<<dim3(8, 16, BB * EE), 256>>>(nullptr, Wo, bo);
    combine_kernel<<<(BB * NN * DD / 4) / 256, 256>>>(out);
}